// round 4
// baseline (speedup 1.0000x reference)
#include <cuda_runtime.h>
#include <math.h>

#define NN 50000
#define EE 800000
#define GG 256
#define EPSF 1e-5f
#define SCAN_B 196   // ceil(50000/256)

// ---------------- scratch ----------------------------------------------------
__device__ __align__(256) float g_hw[NN * 128];     // per-layer message values
__device__ __align__(256) float g_agg[NN * 128];    // activations (post-gelu)
__device__ __align__(256) float g_dis[NN];          // deg^{-1/2}
__device__ __align__(256) float g_t[NN];            // x[n]*dis[n] (layer 0)
__device__ __align__(256) int   g_cnt[NN];
__device__ __align__(256) int   g_rowptr[NN + 1];
__device__ __align__(256) int   g_cur[NN];
__device__ __align__(256) int   g_csr[EE];
__device__ __align__(256) int   g_bsum[SCAN_B];
__device__ __align__(256) float g_stats[384];       // layer l stats at l*128: sum[C], sq[C]
__device__ __align__(256) float g_pool[GG * 128];

__device__ __forceinline__ float geluf(float x) {
    return 0.5f * x * (1.0f + erff(x * 0.70710678118654752f));
}
__device__ __forceinline__ void red_add_v4(float* addr, float a, float b, float c, float d) {
    asm volatile("red.global.add.v4.f32 [%0], {%1,%2,%3,%4};"
                 :: "l"(addr), "f"(a), "f"(b), "f"(c), "f"(d) : "memory");
}

// ---------------- CSR build ---------------------------------------------------
__global__ void k_hist(const int* __restrict__ ei) {
    int e = blockIdx.x * blockDim.x + threadIdx.x;
    if (e < EE) atomicAdd(&g_cnt[ei[EE + e]], 1);
}
__global__ void k_scanA() {
    __shared__ int sh[256];
    int i = blockIdx.x * 256 + threadIdx.x;
    sh[threadIdx.x] = (i < NN) ? g_cnt[i] : 0;
    __syncthreads();
    for (int o = 128; o > 0; o >>= 1) {
        if (threadIdx.x < o) sh[threadIdx.x] += sh[threadIdx.x + o];
        __syncthreads();
    }
    if (threadIdx.x == 0) g_bsum[blockIdx.x] = sh[0];
}
__global__ void k_scanB() {
    __shared__ int sh[256];
    int t = threadIdx.x;
    int v = (t < SCAN_B) ? g_bsum[t] : 0;
    sh[t] = v;
    __syncthreads();
    for (int o = 1; o < 256; o <<= 1) {
        int u = (t >= o) ? sh[t - o] : 0;
        __syncthreads();
        sh[t] += u;
        __syncthreads();
    }
    if (t < SCAN_B) g_bsum[t] = sh[t] - v;
    if (t == 0) g_rowptr[NN] = EE;
}
__global__ void k_scanC(const float* __restrict__ x) {
    __shared__ int sh[256];
    int i = blockIdx.x * 256 + threadIdx.x;
    int t = threadIdx.x;
    int c = (i < NN) ? g_cnt[i] : 0;
    sh[t] = c;
    __syncthreads();
    for (int o = 1; o < 256; o <<= 1) {
        int u = (t >= o) ? sh[t - o] : 0;
        __syncthreads();
        sh[t] += u;
        __syncthreads();
    }
    if (i < NN) {
        int rp = g_bsum[blockIdx.x] + sh[t] - c;
        g_rowptr[i] = rp;
        g_cur[i]    = rp;
        float d = rsqrtf((float)c + 1.0f);
        g_dis[i]  = d;
        g_t[i]    = x[i] * d;
    }
}
__global__ void k_fill(const int* __restrict__ ei) {
    int e = blockIdx.x * blockDim.x + threadIdx.x;
    if (e < EE) {
        int pos = atomicAdd(&g_cur[ei[EE + e]], 1);
        g_csr[pos] = ei[e];
    }
}

// ---------------- layer 0: rank-1 scalar gather + expand + gelu + stats --------
__global__ void k_l0(const float* __restrict__ W1, const float* __restrict__ b1,
                     float* __restrict__ statsOut) {
    int n = blockIdx.x * 256 + threadIdx.x;
    float u = 0.f;
    bool valid = n < NN;
    if (valid) {
        int j = g_rowptr[n], end = g_rowptr[n + 1];
        float s = g_t[n];
        float s0 = 0.f, s1 = 0.f, s2 = 0.f, s3 = 0.f;
        for (; j + 4 <= end; j += 4) {
            s0 += g_t[g_csr[j]];   s1 += g_t[g_csr[j+1]];
            s2 += g_t[g_csr[j+2]]; s3 += g_t[g_csr[j+3]];
        }
        for (; j < end; ++j) s0 += g_t[g_csr[j]];
        u = g_dis[n] * (s + (s0 + s1) + (s2 + s3));
    }
    float sm[16], sq[16], vv[16];
    #pragma unroll
    for (int c = 0; c < 16; ++c) {
        float v = valid ? geluf(fmaf(__ldg(&W1[c]), u, __ldg(&b1[c]))) : 0.f;
        vv[c] = v; sm[c] = v; sq[c] = v * v;
    }
    if (valid) {
        float4* out = (float4*)&g_agg[n * 16];
        out[0] = make_float4(vv[0], vv[1], vv[2], vv[3]);
        out[1] = make_float4(vv[4], vv[5], vv[6], vv[7]);
        out[2] = make_float4(vv[8], vv[9], vv[10], vv[11]);
        out[3] = make_float4(vv[12], vv[13], vv[14], vv[15]);
    }
    #pragma unroll
    for (int off = 16; off > 0; off >>= 1) {
        #pragma unroll
        for (int c = 0; c < 16; ++c) {
            sm[c] += __shfl_xor_sync(0xffffffffu, sm[c], off);
            sq[c] += __shfl_xor_sync(0xffffffffu, sq[c], off);
        }
    }
    if ((threadIdx.x & 31) == 0) {
        #pragma unroll
        for (int c = 0; c < 16; ++c) {
            atomicAdd(&statsOut[c], sm[c]);
            atomicAdd(&statsOut[16 + c], sq[c]);
        }
    }
}

// ---------------- matmul with BN fold inlined ----------------------------------
// hw[n,c] = (sum_i (a[n,i]*sc[i]) * W[i,c] + badd[c]) * dis[n]
template<int Cin, int Cout>
__global__ void k_mmf(const float* __restrict__ in, const float* __restrict__ W,
                      const float* __restrict__ gam, const float* __restrict__ bet,
                      const float* __restrict__ stats) {
    const int NPB = 256 / Cout;                 // nodes per block
    __shared__ float sc[Cin], shf[Cin], badd[Cout], a2[NPB * Cin];
    int tid = threadIdx.x;
    if (tid < Cin) {
        float mu  = stats[tid] * (1.0f / NN);
        float var = stats[Cin + tid] * (1.0f / NN) - mu * mu;
        float s = gam[tid] * rsqrtf(var + EPSF);
        sc[tid]  = s;
        shf[tid] = bet[tid] - mu * s;
    }
    __syncthreads();
    if (tid < Cout) {
        float ba = 0.f;
        #pragma unroll 4
        for (int i = 0; i < Cin; ++i) ba = fmaf(shf[i], W[i * Cout + tid], ba);
        badd[tid] = ba;
    }
    if (tid < NPB * Cin) {
        int node = tid / Cin, i = tid - node * Cin;
        int n = blockIdx.x * NPB + node;
        a2[tid] = (n < NN) ? in[n * Cin + i] * sc[i] : 0.f;
    }
    __syncthreads();
    int node = tid / Cout, c = tid - node * Cout;
    int n = blockIdx.x * NPB + node;
    if (n < NN) {
        const float* a = &a2[node * Cin];
        float s = badd[c];
        #pragma unroll 8
        for (int i = 0; i < Cin; ++i) s = fmaf(a[i], W[i * Cout + c], s);
        g_hw[n * Cout + c] = s * g_dis[n];
    }
}

// ---------------- gather + bias + gelu + BN stats (layers 1-2) -----------------
template<int CQ>
__global__ void k_gather(const float* __restrict__ b, float* __restrict__ statsOut) {
    const int C = 4 * CQ;
    __shared__ float sh[2 * C];
    int tid = threadIdx.x;
    int t = blockIdx.x * 256 + tid;
    bool valid = t < NN * CQ;
    for (int i = tid; i < 2 * C; i += 256) sh[i] = 0.f;
    __syncthreads();

    float4 r = make_float4(0.f, 0.f, 0.f, 0.f);
    if (valid) {
        int n = t / CQ, q = t - n * CQ;
        const float4* __restrict__ hw = (const float4*)g_hw;
        float4 s = hw[n * CQ + q];
        int j = g_rowptr[n], end = g_rowptr[n + 1];
        for (; j + 8 <= end; j += 8) {
            int i0 = g_csr[j],   i1 = g_csr[j+1], i2 = g_csr[j+2], i3 = g_csr[j+3];
            int i4 = g_csr[j+4], i5 = g_csr[j+5], i6 = g_csr[j+6], i7 = g_csr[j+7];
            float4 v0 = hw[i0*CQ+q], v1 = hw[i1*CQ+q], v2 = hw[i2*CQ+q], v3 = hw[i3*CQ+q];
            float4 v4 = hw[i4*CQ+q], v5 = hw[i5*CQ+q], v6 = hw[i6*CQ+q], v7 = hw[i7*CQ+q];
            s.x += ((v0.x+v1.x)+(v2.x+v3.x)) + ((v4.x+v5.x)+(v6.x+v7.x));
            s.y += ((v0.y+v1.y)+(v2.y+v3.y)) + ((v4.y+v5.y)+(v6.y+v7.y));
            s.z += ((v0.z+v1.z)+(v2.z+v3.z)) + ((v4.z+v5.z)+(v6.z+v7.z));
            s.w += ((v0.w+v1.w)+(v2.w+v3.w)) + ((v4.w+v5.w)+(v6.w+v7.w));
        }
        for (; j < end; ++j) {
            float4 v = hw[g_csr[j] * CQ + q];
            s.x += v.x; s.y += v.y; s.z += v.z; s.w += v.w;
        }
        float d = g_dis[n];
        float4 bb = *(const float4*)&b[q * 4];
        r.x = geluf(fmaf(d, s.x, bb.x));
        r.y = geluf(fmaf(d, s.y, bb.y));
        r.z = geluf(fmaf(d, s.z, bb.z));
        r.w = geluf(fmaf(d, s.w, bb.w));
        ((float4*)g_agg)[n * CQ + q] = r;
    }
    float4 r2 = make_float4(r.x * r.x, r.y * r.y, r.z * r.z, r.w * r.w);
    #pragma unroll
    for (int off = CQ; off < 32; off <<= 1) {
        r.x  += __shfl_down_sync(0xffffffffu, r.x,  off);
        r.y  += __shfl_down_sync(0xffffffffu, r.y,  off);
        r.z  += __shfl_down_sync(0xffffffffu, r.z,  off);
        r.w  += __shfl_down_sync(0xffffffffu, r.w,  off);
        r2.x += __shfl_down_sync(0xffffffffu, r2.x, off);
        r2.y += __shfl_down_sync(0xffffffffu, r2.y, off);
        r2.z += __shfl_down_sync(0xffffffffu, r2.z, off);
        r2.w += __shfl_down_sync(0xffffffffu, r2.w, off);
    }
    if ((tid & 31) < CQ) {
        int c0 = (tid % CQ) * 4;
        atomicAdd(&sh[c0 + 0], r.x);  atomicAdd(&sh[C + c0 + 0], r2.x);
        atomicAdd(&sh[c0 + 1], r.y);  atomicAdd(&sh[C + c0 + 1], r2.y);
        atomicAdd(&sh[c0 + 2], r.z);  atomicAdd(&sh[C + c0 + 2], r2.z);
        atomicAdd(&sh[c0 + 3], r.w);  atomicAdd(&sh[C + c0 + 3], r2.w);
    }
    __syncthreads();
    for (int i = tid; i < 2 * C; i += 256) atomicAdd(&statsOut[i], sh[i]);
}

// layer-4 gather: bias + gelu + mean-pool sum fused
__global__ void k_gather_pool(const float* __restrict__ b, const int* __restrict__ batch) {
    const int CQ = 32;
    int t = blockIdx.x * blockDim.x + threadIdx.x;
    if (t >= NN * CQ) return;
    int n = t / CQ, q = t - n * CQ;
    const float4* __restrict__ hw = (const float4*)g_hw;
    float4 s = hw[n * CQ + q];
    int j = g_rowptr[n], end = g_rowptr[n + 1];
    for (; j + 8 <= end; j += 8) {
        int i0 = g_csr[j],   i1 = g_csr[j+1], i2 = g_csr[j+2], i3 = g_csr[j+3];
        int i4 = g_csr[j+4], i5 = g_csr[j+5], i6 = g_csr[j+6], i7 = g_csr[j+7];
        float4 v0 = hw[i0*CQ+q], v1 = hw[i1*CQ+q], v2 = hw[i2*CQ+q], v3 = hw[i3*CQ+q];
        float4 v4 = hw[i4*CQ+q], v5 = hw[i5*CQ+q], v6 = hw[i6*CQ+q], v7 = hw[i7*CQ+q];
        s.x += ((v0.x+v1.x)+(v2.x+v3.x)) + ((v4.x+v5.x)+(v6.x+v7.x));
        s.y += ((v0.y+v1.y)+(v2.y+v3.y)) + ((v4.y+v5.y)+(v6.y+v7.y));
        s.z += ((v0.z+v1.z)+(v2.z+v3.z)) + ((v4.z+v5.z)+(v6.z+v7.z));
        s.w += ((v0.w+v1.w)+(v2.w+v3.w)) + ((v4.w+v5.w)+(v6.w+v7.w));
    }
    for (; j < end; ++j) {
        float4 v = hw[g_csr[j] * CQ + q];
        s.x += v.x; s.y += v.y; s.z += v.z; s.w += v.w;
    }
    float d = g_dis[n];
    float4 bb = *(const float4*)&b[q * 4];
    int g = batch[n];
    red_add_v4(&g_pool[g * 128 + q * 4],
               geluf(fmaf(d, s.x, bb.x)), geluf(fmaf(d, s.y, bb.y)),
               geluf(fmaf(d, s.z, bb.z)), geluf(fmaf(d, s.w, bb.w)));
}

// ---------------- fused MLP head -------------------------------------------------
__global__ void k_head(const int* __restrict__ batch, const float* __restrict__ yx,
                       const float* __restrict__ lw1, const float* __restrict__ lb1,
                       const float* __restrict__ lw2, const float* __restrict__ lb2,
                       const float* __restrict__ lw3, const float* __restrict__ lb3,
                       const float* __restrict__ lw4, const float* __restrict__ lb4,
                       float* __restrict__ out) {
    int g = blockIdx.x, tid = threadIdx.x;
    __shared__ float z[136], a1[128], a2[64], a3[32];
    __shared__ int bounds[2];
    if (tid < 2) {
        int key = g + tid;
        int lo = 0, hi = NN;
        while (lo < hi) {
            int mid = (lo + hi) >> 1;
            if (batch[mid] < key) lo = mid + 1; else hi = mid;
        }
        bounds[tid] = lo;
    }
    __syncthreads();
    float inv = 1.0f / fmaxf((float)(bounds[1] - bounds[0]), 1.0f);
    for (int j = tid; j < 135; j += 128)
        z[j] = (j < 128) ? g_pool[g * 128 + j] * inv : yx[g * 7 + (j - 128)];
    __syncthreads();
    {
        float s = lb1[tid];
        #pragma unroll 5
        for (int i = 0; i < 135; ++i) s = fmaf(z[i], lw1[i * 128 + tid], s);
        a1[tid] = geluf(s);
    }
    __syncthreads();
    if (tid < 64) {
        float s = lb2[tid];
        #pragma unroll 8
        for (int i = 0; i < 128; ++i) s = fmaf(a1[i], lw2[i * 64 + tid], s);
        a2[tid] = geluf(s);
    }
    __syncthreads();
    if (tid < 32) {
        float s = lb3[tid];
        #pragma unroll 8
        for (int i = 0; i < 64; ++i) s = fmaf(a2[i], lw3[i * 32 + tid], s);
        a3[tid] = geluf(s);
    }
    __syncthreads();
    if (tid < 2) {
        float s = lb4[tid];
        #pragma unroll
        for (int i = 0; i < 32; ++i) s = fmaf(a3[i], lw4[i * 2 + tid], s);
        out[g * 2 + tid] = 1.0f / (1.0f + expf(-s));
    }
}

// ---------------- host -------------------------------------------------------------
static inline int gs(int n) { return (n + 255) / 256; }

extern "C" void kernel_launch(void* const* d_in, const int* in_sizes, int n_in,
                              void* d_out, int out_size) {
    const float* x     = (const float*)d_in[0];
    const int*   ei    = (const int*)d_in[1];
    const int*   batch = (const int*)d_in[2];
    const float* yx    = (const float*)d_in[3];
    const float* W[4]  = {(const float*)d_in[4], (const float*)d_in[6],
                          (const float*)d_in[8], (const float*)d_in[10]};
    const float* B[4]  = {(const float*)d_in[5], (const float*)d_in[7],
                          (const float*)d_in[9], (const float*)d_in[11]};
    const float* Gm[3] = {(const float*)d_in[12], (const float*)d_in[14], (const float*)d_in[16]};
    const float* Be[3] = {(const float*)d_in[13], (const float*)d_in[15], (const float*)d_in[17]};
    const float* LW[4] = {(const float*)d_in[18], (const float*)d_in[20],
                          (const float*)d_in[22], (const float*)d_in[24]};
    const float* LB[4] = {(const float*)d_in[19], (const float*)d_in[21],
                          (const float*)d_in[23], (const float*)d_in[25]};

    void *p_cnt, *p_agg, *p_pool, *p_stats;
    cudaGetSymbolAddress(&p_cnt,   g_cnt);
    cudaGetSymbolAddress(&p_agg,   g_agg);
    cudaGetSymbolAddress(&p_pool,  g_pool);
    cudaGetSymbolAddress(&p_stats, g_stats);
    float* stats = (float*)p_stats;

    cudaMemsetAsync(p_cnt,   0, NN * sizeof(int));
    cudaMemsetAsync(p_pool,  0, GG * 128 * sizeof(float));
    cudaMemsetAsync(p_stats, 0, 384 * sizeof(float));

    k_hist <<<gs(EE), 256>>>(ei);
    k_scanA<<<SCAN_B, 256>>>();
    k_scanB<<<1, 256>>>();
    k_scanC<<<SCAN_B, 256>>>(x);
    k_fill <<<gs(EE), 256>>>(ei);

    // layer 0 (conv1): rank-1 fused
    k_l0<<<gs(NN), 256>>>(W[0], B[0], stats + 0);

    // layer 1 (conv2): 16 -> 32
    k_mmf<16, 32><<<gs(NN * 32), 256>>>((const float*)p_agg, W[1], Gm[0], Be[0], stats + 0);
    k_gather<8><<<gs(NN * 8), 256>>>(B[1], stats + 128);

    // layer 2 (conv3): 32 -> 64
    k_mmf<32, 64><<<gs(NN * 64), 256>>>((const float*)p_agg, W[2], Gm[1], Be[1], stats + 128);
    k_gather<16><<<gs(NN * 16), 256>>>(B[2], stats + 256);

    // layer 3 (conv4): 64 -> 128, pool fused
    k_mmf<64, 128><<<gs(NN * 128), 256>>>((const float*)p_agg, W[3], Gm[2], Be[2], stats + 256);
    k_gather_pool<<<gs(NN * 32), 256>>>(B[3], batch);

    k_head<<<GG, 128>>>(batch, yx, LW[0], LB[0], LW[1], LB[1],
                        LW[2], LB[2], LW[3], LB[3], (float*)d_out);
}

// round 5
// speedup vs baseline: 1.2356x; 1.2356x over previous
#include <cuda_runtime.h>
#include <cuda_fp16.h>
#include <math.h>

#define NN 50000
#define EE 800000
#define GG 256
#define EPSF 1e-5f
#define SCAN_B 196   // ceil(50000/256)

// ---------------- scratch ----------------------------------------------------
__device__ __align__(256) float  g_hw[NN * 64];     // fp32 messages (layers 1-2)
__device__ __align__(256) __half g_hwh[NN * 128];   // fp16 messages (layer 3)
__device__ __align__(256) float  g_agg[NN * 64];    // activations (post-gelu)
__device__ __align__(256) float  g_dis[NN];
__device__ __align__(256) float  g_t[NN];           // x[n]*dis[n]
__device__ __align__(256) int    g_cnt[NN];
__device__ __align__(256) int    g_rowptr[NN + 1];
__device__ __align__(256) int    g_cur[NN];
__device__ __align__(256) int    g_csr[EE];
__device__ __align__(256) int    g_bsum[SCAN_B];
__device__ __align__(256) float  g_stats[384];
__device__ __align__(256) float  g_wf[64 * 128];    // folded weights
__device__ __align__(256) float  g_badd[128];       // folded bias-add
__device__ __align__(256) float  g_pool[GG * 128];

__device__ __forceinline__ float geluf(float x) {
    return 0.5f * x * (1.0f + erff(x * 0.70710678118654752f));
}
__device__ __forceinline__ void red_add_v4(float* addr, float a, float b, float c, float d) {
    asm volatile("red.global.add.v4.f32 [%0], {%1,%2,%3,%4};"
                 :: "l"(addr), "f"(a), "f"(b), "f"(c), "f"(d) : "memory");
}

// ---------------- CSR build ---------------------------------------------------
__global__ void k_hist(const int* __restrict__ ei) {
    int e = blockIdx.x * blockDim.x + threadIdx.x;
    if (e < EE) atomicAdd(&g_cnt[ei[EE + e]], 1);
}
__global__ void k_scanA() {
    __shared__ int sh[256];
    int i = blockIdx.x * 256 + threadIdx.x;
    sh[threadIdx.x] = (i < NN) ? g_cnt[i] : 0;
    __syncthreads();
    for (int o = 128; o > 0; o >>= 1) {
        if (threadIdx.x < o) sh[threadIdx.x] += sh[threadIdx.x + o];
        __syncthreads();
    }
    if (threadIdx.x == 0) g_bsum[blockIdx.x] = sh[0];
}
__global__ void k_scanB() {
    __shared__ int sh[256];
    int t = threadIdx.x;
    int v = (t < SCAN_B) ? g_bsum[t] : 0;
    sh[t] = v;
    __syncthreads();
    for (int o = 1; o < 256; o <<= 1) {
        int u = (t >= o) ? sh[t - o] : 0;
        __syncthreads();
        sh[t] += u;
        __syncthreads();
    }
    if (t < SCAN_B) g_bsum[t] = sh[t] - v;
    if (t == 0) g_rowptr[NN] = EE;
}
__global__ void k_scanC(const float* __restrict__ x) {
    __shared__ int sh[256];
    int i = blockIdx.x * 256 + threadIdx.x;
    int t = threadIdx.x;
    int c = (i < NN) ? g_cnt[i] : 0;
    sh[t] = c;
    __syncthreads();
    for (int o = 1; o < 256; o <<= 1) {
        int u = (t >= o) ? sh[t - o] : 0;
        __syncthreads();
        sh[t] += u;
        __syncthreads();
    }
    if (i < NN) {
        int rp = g_bsum[blockIdx.x] + sh[t] - c;
        g_rowptr[i] = rp;
        g_cur[i]    = rp;
        float d = rsqrtf((float)c + 1.0f);
        g_dis[i]  = d;
        g_t[i]    = x[i] * d;
    }
}
__global__ void k_fill(const int* __restrict__ ei) {
    int e = blockIdx.x * blockDim.x + threadIdx.x;
    if (e < EE) {
        int pos = atomicAdd(&g_cur[ei[EE + e]], 1);
        g_csr[pos] = ei[e];
    }
}

// ---------------- layer 0: rank-1 scalar gather + expand + gelu + stats --------
__global__ void k_l0(const float* __restrict__ W1, const float* __restrict__ b1,
                     float* __restrict__ statsOut) {
    int n = blockIdx.x * 256 + threadIdx.x;
    float u = 0.f;
    bool valid = n < NN;
    if (valid) {
        int j = g_rowptr[n], end = g_rowptr[n + 1];
        float s = g_t[n];
        float s0 = 0.f, s1 = 0.f, s2 = 0.f, s3 = 0.f;
        for (; j + 4 <= end; j += 4) {
            s0 += g_t[g_csr[j]];   s1 += g_t[g_csr[j+1]];
            s2 += g_t[g_csr[j+2]]; s3 += g_t[g_csr[j+3]];
        }
        for (; j < end; ++j) s0 += g_t[g_csr[j]];
        u = g_dis[n] * (s + (s0 + s1) + (s2 + s3));
    }
    float sm[16], sq[16], vv[16];
    #pragma unroll
    for (int c = 0; c < 16; ++c) {
        float v = valid ? geluf(fmaf(__ldg(&W1[c]), u, __ldg(&b1[c]))) : 0.f;
        vv[c] = v; sm[c] = v; sq[c] = v * v;
    }
    if (valid) {
        float4* out = (float4*)&g_agg[n * 16];
        out[0] = make_float4(vv[0], vv[1], vv[2], vv[3]);
        out[1] = make_float4(vv[4], vv[5], vv[6], vv[7]);
        out[2] = make_float4(vv[8], vv[9], vv[10], vv[11]);
        out[3] = make_float4(vv[12], vv[13], vv[14], vv[15]);
    }
    #pragma unroll
    for (int off = 16; off > 0; off >>= 1) {
        #pragma unroll
        for (int c = 0; c < 16; ++c) {
            sm[c] += __shfl_xor_sync(0xffffffffu, sm[c], off);
            sq[c] += __shfl_xor_sync(0xffffffffu, sq[c], off);
        }
    }
    if ((threadIdx.x & 31) == 0) {
        #pragma unroll
        for (int c = 0; c < 16; ++c) {
            atomicAdd(&statsOut[c], sm[c]);
            atomicAdd(&statsOut[16 + c], sq[c]);
        }
    }
}

// ---------------- BN fold (once per layer): g_wf = sc*W, g_badd = shf@W --------
template<int Cin, int Cout>
__global__ void k_fold(const float* __restrict__ gam, const float* __restrict__ bet,
                       const float* __restrict__ W, const float* __restrict__ stats) {
    __shared__ float sc[64], shf[64];
    int tid = threadIdx.x;
    if (tid < Cin) {
        float mu  = stats[tid] * (1.0f / NN);
        float var = stats[Cin + tid] * (1.0f / NN) - mu * mu;
        float s = gam[tid] * rsqrtf(var + EPSF);
        sc[tid]  = s;
        shf[tid] = bet[tid] - mu * s;
    }
    __syncthreads();
    for (int j = blockIdx.x * 256 + tid; j < Cin * Cout; j += gridDim.x * 256)
        g_wf[j] = sc[j / Cout] * W[j];
    if (blockIdx.x == 0 && tid < Cout) {
        float ba = 0.f;
        #pragma unroll 4
        for (int i = 0; i < Cin; ++i) ba = fmaf(shf[i], W[i * Cout + tid], ba);
        g_badd[tid] = ba;
    }
}

// ---------------- matmul: thread = (node, channel-quad), folded W + badd -------
// hw[n, c4] = (a[n,:] @ wf[:, c4] + badd[c4]) * dis[n]
template<int Cin, int Cout, bool HALF_OUT>
__global__ void k_mm4(const float* __restrict__ in) {
    const int CQ = Cout / 4;
    int t = blockIdx.x * blockDim.x + threadIdx.x;
    if (t >= NN * CQ) return;
    int n = t / CQ, c4 = t - n * CQ;
    const float4* __restrict__ Wv = (const float4*)g_wf;
    const float* __restrict__ a = in + n * Cin;
    float4 s = ((const float4*)g_badd)[c4];
    #pragma unroll
    for (int i = 0; i < Cin; ++i) {
        float av = a[i];
        float4 w = Wv[i * CQ + c4];
        s.x = fmaf(av, w.x, s.x); s.y = fmaf(av, w.y, s.y);
        s.z = fmaf(av, w.z, s.z); s.w = fmaf(av, w.w, s.w);
    }
    float d = g_dis[n];
    s.x *= d; s.y *= d; s.z *= d; s.w *= d;
    if (HALF_OUT) {
        __half2 h0 = __floats2half2_rn(s.x, s.y);
        __half2 h1 = __floats2half2_rn(s.z, s.w);
        uint2 u;
        u.x = *(unsigned*)&h0; u.y = *(unsigned*)&h1;
        ((uint2*)g_hwh)[t] = u;
    } else {
        ((float4*)g_hw)[t] = s;
    }
}

// ---------------- gather + bias + gelu + BN stats (layers 1-2, fp32) ----------
template<int CQ>
__global__ void k_gather(const float* __restrict__ b, float* __restrict__ statsOut) {
    const int C = 4 * CQ;
    __shared__ float sh[2 * C];
    int tid = threadIdx.x;
    int t = blockIdx.x * 256 + tid;
    bool valid = t < NN * CQ;
    for (int i = tid; i < 2 * C; i += 256) sh[i] = 0.f;
    __syncthreads();

    float4 r = make_float4(0.f, 0.f, 0.f, 0.f);
    if (valid) {
        int n = t / CQ, q = t - n * CQ;
        const float4* __restrict__ hw = (const float4*)g_hw;
        float4 s = hw[n * CQ + q];
        int j = g_rowptr[n], end = g_rowptr[n + 1];
        for (; j + 8 <= end; j += 8) {
            int i0 = g_csr[j],   i1 = g_csr[j+1], i2 = g_csr[j+2], i3 = g_csr[j+3];
            int i4 = g_csr[j+4], i5 = g_csr[j+5], i6 = g_csr[j+6], i7 = g_csr[j+7];
            float4 v0 = hw[i0*CQ+q], v1 = hw[i1*CQ+q], v2 = hw[i2*CQ+q], v3 = hw[i3*CQ+q];
            float4 v4 = hw[i4*CQ+q], v5 = hw[i5*CQ+q], v6 = hw[i6*CQ+q], v7 = hw[i7*CQ+q];
            s.x += ((v0.x+v1.x)+(v2.x+v3.x)) + ((v4.x+v5.x)+(v6.x+v7.x));
            s.y += ((v0.y+v1.y)+(v2.y+v3.y)) + ((v4.y+v5.y)+(v6.y+v7.y));
            s.z += ((v0.z+v1.z)+(v2.z+v3.z)) + ((v4.z+v5.z)+(v6.z+v7.z));
            s.w += ((v0.w+v1.w)+(v2.w+v3.w)) + ((v4.w+v5.w)+(v6.w+v7.w));
        }
        for (; j < end; ++j) {
            float4 v = hw[g_csr[j] * CQ + q];
            s.x += v.x; s.y += v.y; s.z += v.z; s.w += v.w;
        }
        float d = g_dis[n];
        float4 bb = *(const float4*)&b[q * 4];
        r.x = geluf(fmaf(d, s.x, bb.x));
        r.y = geluf(fmaf(d, s.y, bb.y));
        r.z = geluf(fmaf(d, s.z, bb.z));
        r.w = geluf(fmaf(d, s.w, bb.w));
        ((float4*)g_agg)[n * CQ + q] = r;
    }
    float4 r2 = make_float4(r.x * r.x, r.y * r.y, r.z * r.z, r.w * r.w);
    #pragma unroll
    for (int off = CQ; off < 32; off <<= 1) {
        r.x  += __shfl_down_sync(0xffffffffu, r.x,  off);
        r.y  += __shfl_down_sync(0xffffffffu, r.y,  off);
        r.z  += __shfl_down_sync(0xffffffffu, r.z,  off);
        r.w  += __shfl_down_sync(0xffffffffu, r.w,  off);
        r2.x += __shfl_down_sync(0xffffffffu, r2.x, off);
        r2.y += __shfl_down_sync(0xffffffffu, r2.y, off);
        r2.z += __shfl_down_sync(0xffffffffu, r2.z, off);
        r2.w += __shfl_down_sync(0xffffffffu, r2.w, off);
    }
    if ((tid & 31) < CQ) {
        int c0 = (tid % CQ) * 4;
        atomicAdd(&sh[c0 + 0], r.x);  atomicAdd(&sh[C + c0 + 0], r2.x);
        atomicAdd(&sh[c0 + 1], r.y);  atomicAdd(&sh[C + c0 + 1], r2.y);
        atomicAdd(&sh[c0 + 2], r.z);  atomicAdd(&sh[C + c0 + 2], r2.z);
        atomicAdd(&sh[c0 + 3], r.w);  atomicAdd(&sh[C + c0 + 3], r2.w);
    }
    __syncthreads();
    for (int i = tid; i < 2 * C; i += 256) atomicAdd(&statsOut[i], sh[i]);
}

// ---------------- layer-3 gather (fp16 msgs) + bias + gelu + pool --------------
__global__ void k_gather_pool_h(const float* __restrict__ b, const int* __restrict__ batch) {
    const int CQ = 32;   // 32 quads of 4 half-channels
    int t = blockIdx.x * blockDim.x + threadIdx.x;
    if (t >= NN * CQ) return;
    int n = t / CQ, q = t - n * CQ;
    const uint2* __restrict__ hw = (const uint2*)g_hwh;   // row = 32 uint2 (128 halves)
    float4 s;
    {
        uint2 u = hw[n * CQ + q];
        float2 f0 = __half22float2(*(__half2*)&u.x);
        float2 f1 = __half22float2(*(__half2*)&u.y);
        s = make_float4(f0.x, f0.y, f1.x, f1.y);
    }
    int j = g_rowptr[n], end = g_rowptr[n + 1];
    for (; j + 8 <= end; j += 8) {
        int i0 = g_csr[j],   i1 = g_csr[j+1], i2 = g_csr[j+2], i3 = g_csr[j+3];
        int i4 = g_csr[j+4], i5 = g_csr[j+5], i6 = g_csr[j+6], i7 = g_csr[j+7];
        uint2 u0 = hw[i0*CQ+q], u1 = hw[i1*CQ+q], u2 = hw[i2*CQ+q], u3 = hw[i3*CQ+q];
        uint2 u4 = hw[i4*CQ+q], u5 = hw[i5*CQ+q], u6 = hw[i6*CQ+q], u7 = hw[i7*CQ+q];
        #pragma unroll
        for (int k = 0; k < 8; ++k) {
            uint2 u = (k==0)?u0:(k==1)?u1:(k==2)?u2:(k==3)?u3:(k==4)?u4:(k==5)?u5:(k==6)?u6:u7;
            float2 f0 = __half22float2(*(__half2*)&u.x);
            float2 f1 = __half22float2(*(__half2*)&u.y);
            s.x += f0.x; s.y += f0.y; s.z += f1.x; s.w += f1.y;
        }
    }
    for (; j < end; ++j) {
        uint2 u = hw[g_csr[j] * CQ + q];
        float2 f0 = __half22float2(*(__half2*)&u.x);
        float2 f1 = __half22float2(*(__half2*)&u.y);
        s.x += f0.x; s.y += f0.y; s.z += f1.x; s.w += f1.y;
    }
    float d = g_dis[n];
    float4 bb = *(const float4*)&b[q * 4];
    int g = batch[n];
    red_add_v4(&g_pool[g * 128 + q * 4],
               geluf(fmaf(d, s.x, bb.x)), geluf(fmaf(d, s.y, bb.y)),
               geluf(fmaf(d, s.z, bb.z)), geluf(fmaf(d, s.w, bb.w)));
}

// ---------------- fused MLP head -------------------------------------------------
__global__ void k_head(const int* __restrict__ batch, const float* __restrict__ yx,
                       const float* __restrict__ lw1, const float* __restrict__ lb1,
                       const float* __restrict__ lw2, const float* __restrict__ lb2,
                       const float* __restrict__ lw3, const float* __restrict__ lb3,
                       const float* __restrict__ lw4, const float* __restrict__ lb4,
                       float* __restrict__ out) {
    int g = blockIdx.x, tid = threadIdx.x;
    __shared__ float z[136], a1[128], a2[64], a3[32];
    __shared__ int bounds[2];
    if (tid < 2) {
        int key = g + tid;
        int lo = 0, hi = NN;
        while (lo < hi) {
            int mid = (lo + hi) >> 1;
            if (batch[mid] < key) lo = mid + 1; else hi = mid;
        }
        bounds[tid] = lo;
    }
    __syncthreads();
    float inv = 1.0f / fmaxf((float)(bounds[1] - bounds[0]), 1.0f);
    for (int j = tid; j < 135; j += 128)
        z[j] = (j < 128) ? g_pool[g * 128 + j] * inv : yx[g * 7 + (j - 128)];
    __syncthreads();
    {
        float s = lb1[tid];
        #pragma unroll 5
        for (int i = 0; i < 135; ++i) s = fmaf(z[i], lw1[i * 128 + tid], s);
        a1[tid] = geluf(s);
    }
    __syncthreads();
    if (tid < 64) {
        float s = lb2[tid];
        #pragma unroll 8
        for (int i = 0; i < 128; ++i) s = fmaf(a1[i], lw2[i * 64 + tid], s);
        a2[tid] = geluf(s);
    }
    __syncthreads();
    if (tid < 32) {
        float s = lb3[tid];
        #pragma unroll 8
        for (int i = 0; i < 64; ++i) s = fmaf(a2[i], lw3[i * 32 + tid], s);
        a3[tid] = geluf(s);
    }
    __syncthreads();
    if (tid < 2) {
        float s = lb4[tid];
        #pragma unroll
        for (int i = 0; i < 32; ++i) s = fmaf(a3[i], lw4[i * 2 + tid], s);
        out[g * 2 + tid] = 1.0f / (1.0f + expf(-s));
    }
}

// ---------------- host -------------------------------------------------------------
static inline int gs(int n) { return (n + 255) / 256; }

extern "C" void kernel_launch(void* const* d_in, const int* in_sizes, int n_in,
                              void* d_out, int out_size) {
    const float* x     = (const float*)d_in[0];
    const int*   ei    = (const int*)d_in[1];
    const int*   batch = (const int*)d_in[2];
    const float* yx    = (const float*)d_in[3];
    const float* W[4]  = {(const float*)d_in[4], (const float*)d_in[6],
                          (const float*)d_in[8], (const float*)d_in[10]};
    const float* B[4]  = {(const float*)d_in[5], (const float*)d_in[7],
                          (const float*)d_in[9], (const float*)d_in[11]};
    const float* Gm[3] = {(const float*)d_in[12], (const float*)d_in[14], (const float*)d_in[16]};
    const float* Be[3] = {(const float*)d_in[13], (const float*)d_in[15], (const float*)d_in[17]};
    const float* LW[4] = {(const float*)d_in[18], (const float*)d_in[20],
                          (const float*)d_in[22], (const float*)d_in[24]};
    const float* LB[4] = {(const float*)d_in[19], (const float*)d_in[21],
                          (const float*)d_in[23], (const float*)d_in[25]};

    void *p_cnt, *p_agg, *p_pool, *p_stats;
    cudaGetSymbolAddress(&p_cnt,   g_cnt);
    cudaGetSymbolAddress(&p_agg,   g_agg);
    cudaGetSymbolAddress(&p_pool,  g_pool);
    cudaGetSymbolAddress(&p_stats, g_stats);
    float* stats = (float*)p_stats;

    cudaMemsetAsync(p_cnt,   0, NN * sizeof(int));
    cudaMemsetAsync(p_pool,  0, GG * 128 * sizeof(float));
    cudaMemsetAsync(p_stats, 0, 384 * sizeof(float));

    k_hist <<<gs(EE), 256>>>(ei);
    k_scanA<<<SCAN_B, 256>>>();
    k_scanB<<<1, 256>>>();
    k_scanC<<<SCAN_B, 256>>>(x);
    k_fill <<<gs(EE), 256>>>(ei);

    // layer 0 (conv1): rank-1 fused
    k_l0<<<gs(NN), 256>>>(W[0], B[0], stats + 0);

    // layer 1 (conv2): 16 -> 32
    k_fold<16, 32><<<2, 256>>>(Gm[0], Be[0], W[1], stats + 0);
    k_mm4<16, 32, false><<<gs(NN * 8), 256>>>((const float*)p_agg);
    k_gather<8><<<gs(NN * 8), 256>>>(B[1], stats + 128);

    // layer 2 (conv3): 32 -> 64
    k_fold<32, 64><<<8, 256>>>(Gm[1], Be[1], W[2], stats + 128);
    k_mm4<32, 64, false><<<gs(NN * 16), 256>>>((const float*)p_agg);
    k_gather<16><<<gs(NN * 16), 256>>>(B[2], stats + 256);

    // layer 3 (conv4): 64 -> 128, fp16 messages, pool fused
    k_fold<64, 128><<<32, 256>>>(Gm[2], Be[2], W[3], stats + 256);
    k_mm4<64, 128, true><<<gs(NN * 32), 256>>>((const float*)p_agg);
    k_gather_pool_h<<<gs(NN * 32), 256>>>(B[3], batch);

    k_head<<<GG, 128>>>(batch, yx, LW[0], LB[0], LW[1], LB[1],
                        LW[2], LB[2], LW[3], LB[3], (float*)d_out);
}

// round 6
// speedup vs baseline: 1.2491x; 1.0109x over previous
#include <cuda_runtime.h>
#include <cuda_fp16.h>
#include <math.h>

#define NN 50000
#define EE 800000
#define GG 256
#define EPSF 1e-5f
#define SCAN_B 196   // ceil(50000/256)

// ---------------- scratch ----------------------------------------------------
__device__ __align__(256) __half g_hwh[NN * 128];   // fp16 messages (all layers)
__device__ __align__(256) float  g_agg[NN * 64];    // activations (post-gelu)
__device__ __align__(256) float  g_dis[NN];
__device__ __align__(256) float  g_t[NN];           // x[n]*dis[n]
__device__ __align__(256) int    g_cnt[NN];
__device__ __align__(256) int    g_rowptr[NN + 1];
__device__ __align__(256) int    g_cur[NN];
__device__ __align__(256) int    g_csr[EE];
__device__ __align__(256) int    g_bsum[SCAN_B];
__device__ __align__(256) float  g_stats[384];
__device__ __align__(256) float  g_wf[64 * 128];    // folded weights
__device__ __align__(256) float  g_badd[128];       // folded bias-add
__device__ __align__(256) float  g_pool[GG * 128];

__device__ __forceinline__ float geluf(float x) {
    return 0.5f * x * (1.0f + erff(x * 0.70710678118654752f));
}
__device__ __forceinline__ void red_add_v4(float* addr, float a, float b, float c, float d) {
    asm volatile("red.global.add.v4.f32 [%0], {%1,%2,%3,%4};"
                 :: "l"(addr), "f"(a), "f"(b), "f"(c), "f"(d) : "memory");
}
__device__ __forceinline__ void acc_h(float4& s, uint2 u) {
    float2 f0 = __half22float2(*(__half2*)&u.x);
    float2 f1 = __half22float2(*(__half2*)&u.y);
    s.x += f0.x; s.y += f0.y; s.z += f1.x; s.w += f1.y;
}

// ---------------- CSR build ---------------------------------------------------
__global__ void k_hist(const int* __restrict__ ei) {
    int e = blockIdx.x * blockDim.x + threadIdx.x;
    if (e < EE) atomicAdd(&g_cnt[ei[EE + e]], 1);
}
__global__ void k_scanA() {
    __shared__ int sh[256];
    int i = blockIdx.x * 256 + threadIdx.x;
    sh[threadIdx.x] = (i < NN) ? g_cnt[i] : 0;
    __syncthreads();
    for (int o = 128; o > 0; o >>= 1) {
        if (threadIdx.x < o) sh[threadIdx.x] += sh[threadIdx.x + o];
        __syncthreads();
    }
    if (threadIdx.x == 0) g_bsum[blockIdx.x] = sh[0];
}
__global__ void k_scanB() {
    __shared__ int sh[256];
    int t = threadIdx.x;
    int v = (t < SCAN_B) ? g_bsum[t] : 0;
    sh[t] = v;
    __syncthreads();
    for (int o = 1; o < 256; o <<= 1) {
        int u = (t >= o) ? sh[t - o] : 0;
        __syncthreads();
        sh[t] += u;
        __syncthreads();
    }
    if (t < SCAN_B) g_bsum[t] = sh[t] - v;
    if (t == 0) g_rowptr[NN] = EE;
}
__global__ void k_scanC(const float* __restrict__ x) {
    __shared__ int sh[256];
    int i = blockIdx.x * 256 + threadIdx.x;
    int t = threadIdx.x;
    int c = (i < NN) ? g_cnt[i] : 0;
    sh[t] = c;
    __syncthreads();
    for (int o = 1; o < 256; o <<= 1) {
        int u = (t >= o) ? sh[t - o] : 0;
        __syncthreads();
        sh[t] += u;
        __syncthreads();
    }
    if (i < NN) {
        int rp = g_bsum[blockIdx.x] + sh[t] - c;
        g_rowptr[i] = rp;
        g_cur[i]    = rp;
        float d = rsqrtf((float)c + 1.0f);
        g_dis[i]  = d;
        g_t[i]    = x[i] * d;
    }
}
__global__ void k_fill(const int* __restrict__ ei) {
    int e = blockIdx.x * blockDim.x + threadIdx.x;
    if (e < EE) {
        int pos = atomicAdd(&g_cur[ei[EE + e]], 1);
        g_csr[pos] = ei[e];
    }
}

// ---------------- layer 0: rank-1 scalar gather + expand + gelu + stats --------
__global__ void k_l0(const float* __restrict__ W1, const float* __restrict__ b1,
                     float* __restrict__ statsOut) {
    int n = blockIdx.x * 256 + threadIdx.x;
    float u = 0.f;
    bool valid = n < NN;
    if (valid) {
        int j = g_rowptr[n], end = g_rowptr[n + 1];
        float s = g_t[n];
        float s0 = 0.f, s1 = 0.f, s2 = 0.f, s3 = 0.f;
        while (j < end && (j & 3)) s0 += g_t[g_csr[j++]];
        for (; j + 4 <= end; j += 4) {
            int4 i4 = *(const int4*)&g_csr[j];
            s0 += g_t[i4.x]; s1 += g_t[i4.y];
            s2 += g_t[i4.z]; s3 += g_t[i4.w];
        }
        for (; j < end; ++j) s0 += g_t[g_csr[j]];
        u = g_dis[n] * (s + (s0 + s1) + (s2 + s3));
    }
    float sm[16], sq[16], vv[16];
    #pragma unroll
    for (int c = 0; c < 16; ++c) {
        float v = valid ? geluf(fmaf(__ldg(&W1[c]), u, __ldg(&b1[c]))) : 0.f;
        vv[c] = v; sm[c] = v; sq[c] = v * v;
    }
    if (valid) {
        float4* out = (float4*)&g_agg[n * 16];
        out[0] = make_float4(vv[0], vv[1], vv[2], vv[3]);
        out[1] = make_float4(vv[4], vv[5], vv[6], vv[7]);
        out[2] = make_float4(vv[8], vv[9], vv[10], vv[11]);
        out[3] = make_float4(vv[12], vv[13], vv[14], vv[15]);
    }
    #pragma unroll
    for (int off = 16; off > 0; off >>= 1) {
        #pragma unroll
        for (int c = 0; c < 16; ++c) {
            sm[c] += __shfl_xor_sync(0xffffffffu, sm[c], off);
            sq[c] += __shfl_xor_sync(0xffffffffu, sq[c], off);
        }
    }
    if ((threadIdx.x & 31) == 0) {
        #pragma unroll
        for (int c = 0; c < 16; ++c) {
            atomicAdd(&statsOut[c], sm[c]);
            atomicAdd(&statsOut[16 + c], sq[c]);
        }
    }
}

// ---------------- BN fold (once per layer): g_wf = sc*W, g_badd = shf@W --------
template<int Cin, int Cout>
__global__ void k_fold(const float* __restrict__ gam, const float* __restrict__ bet,
                       const float* __restrict__ W, const float* __restrict__ stats) {
    __shared__ float sc[64], shf[64];
    int tid = threadIdx.x;
    if (tid < Cin) {
        float mu  = stats[tid] * (1.0f / NN);
        float var = stats[Cin + tid] * (1.0f / NN) - mu * mu;
        float s = gam[tid] * rsqrtf(var + EPSF);
        sc[tid]  = s;
        shf[tid] = bet[tid] - mu * s;
    }
    __syncthreads();
    for (int j = blockIdx.x * 256 + tid; j < Cin * Cout; j += gridDim.x * 256)
        g_wf[j] = sc[j / Cout] * W[j];
    if (blockIdx.x == 0 && tid < Cout) {
        float ba = 0.f;
        #pragma unroll 4
        for (int i = 0; i < Cin; ++i) ba = fmaf(shf[i], W[i * Cout + tid], ba);
        g_badd[tid] = ba;
    }
}

// ---------------- matmul -> fp16 messages --------------------------------------
// hwh[n, c4] = half4( (a[n,:] @ wf[:, c4] + badd[c4]) * dis[n] )
template<int Cin, int Cout>
__global__ void k_mm4(const float* __restrict__ in) {
    const int CQ = Cout / 4;
    int t = blockIdx.x * blockDim.x + threadIdx.x;
    if (t >= NN * CQ) return;
    int n = t / CQ, c4 = t - n * CQ;
    const float4* __restrict__ Wv = (const float4*)g_wf;
    const float* __restrict__ a = in + n * Cin;
    float4 s = ((const float4*)g_badd)[c4];
    #pragma unroll
    for (int i = 0; i < Cin; ++i) {
        float av = a[i];
        float4 w = Wv[i * CQ + c4];
        s.x = fmaf(av, w.x, s.x); s.y = fmaf(av, w.y, s.y);
        s.z = fmaf(av, w.z, s.z); s.w = fmaf(av, w.w, s.w);
    }
    float d = g_dis[n];
    __half2 h0 = __floats2half2_rn(s.x * d, s.y * d);
    __half2 h1 = __floats2half2_rn(s.z * d, s.w * d);
    uint2 u;
    u.x = *(unsigned*)&h0; u.y = *(unsigned*)&h1;
    ((uint2*)g_hwh)[t] = u;
}

// ---------------- gather (fp16 msgs, int4 csr) + gelu + BN stats (layers 1-2) --
template<int W>
__global__ void k_gather(const float* __restrict__ bias, float* __restrict__ statsOut) {
    const int C = 4 * W;
    __shared__ float sh[2 * C];
    int tid = threadIdx.x;
    int t = blockIdx.x * 256 + tid;
    bool valid = t < NN * W;
    for (int i = tid; i < 2 * C; i += 256) sh[i] = 0.f;
    __syncthreads();

    float4 r = make_float4(0.f, 0.f, 0.f, 0.f);
    if (valid) {
        int n = t / W, q = t - n * W;
        const uint2* __restrict__ hw = (const uint2*)g_hwh;
        float4 s;
        { uint2 u = hw[n * W + q];
          float2 f0 = __half22float2(*(__half2*)&u.x);
          float2 f1 = __half22float2(*(__half2*)&u.y);
          s = make_float4(f0.x, f0.y, f1.x, f1.y); }
        int j = g_rowptr[n], end = g_rowptr[n + 1];
        while (j < end && (j & 3)) acc_h(s, hw[g_csr[j++] * W + q]);
        for (; j + 8 <= end; j += 8) {
            int4 a4 = *(const int4*)&g_csr[j];
            int4 b4 = *(const int4*)&g_csr[j + 4];
            uint2 u0 = hw[a4.x*W+q], u1 = hw[a4.y*W+q], u2 = hw[a4.z*W+q], u3 = hw[a4.w*W+q];
            uint2 u4 = hw[b4.x*W+q], u5 = hw[b4.y*W+q], u6 = hw[b4.z*W+q], u7 = hw[b4.w*W+q];
            acc_h(s, u0); acc_h(s, u1); acc_h(s, u2); acc_h(s, u3);
            acc_h(s, u4); acc_h(s, u5); acc_h(s, u6); acc_h(s, u7);
        }
        if (j + 4 <= end) {
            int4 a4 = *(const int4*)&g_csr[j];
            uint2 u0 = hw[a4.x*W+q], u1 = hw[a4.y*W+q], u2 = hw[a4.z*W+q], u3 = hw[a4.w*W+q];
            acc_h(s, u0); acc_h(s, u1); acc_h(s, u2); acc_h(s, u3);
            j += 4;
        }
        for (; j < end; ++j) acc_h(s, hw[g_csr[j] * W + q]);
        float d = g_dis[n];
        float4 bb = *(const float4*)&bias[q * 4];
        r.x = geluf(fmaf(d, s.x, bb.x));
        r.y = geluf(fmaf(d, s.y, bb.y));
        r.z = geluf(fmaf(d, s.z, bb.z));
        r.w = geluf(fmaf(d, s.w, bb.w));
        ((float4*)g_agg)[n * W + q] = r;
    }
    float4 r2 = make_float4(r.x * r.x, r.y * r.y, r.z * r.z, r.w * r.w);
    #pragma unroll
    for (int off = W; off < 32; off <<= 1) {
        r.x  += __shfl_down_sync(0xffffffffu, r.x,  off);
        r.y  += __shfl_down_sync(0xffffffffu, r.y,  off);
        r.z  += __shfl_down_sync(0xffffffffu, r.z,  off);
        r.w  += __shfl_down_sync(0xffffffffu, r.w,  off);
        r2.x += __shfl_down_sync(0xffffffffu, r2.x, off);
        r2.y += __shfl_down_sync(0xffffffffu, r2.y, off);
        r2.z += __shfl_down_sync(0xffffffffu, r2.z, off);
        r2.w += __shfl_down_sync(0xffffffffu, r2.w, off);
    }
    if ((tid & 31) < W) {
        int c0 = (tid % W) * 4;
        atomicAdd(&sh[c0 + 0], r.x);  atomicAdd(&sh[C + c0 + 0], r2.x);
        atomicAdd(&sh[c0 + 1], r.y);  atomicAdd(&sh[C + c0 + 1], r2.y);
        atomicAdd(&sh[c0 + 2], r.z);  atomicAdd(&sh[C + c0 + 2], r2.z);
        atomicAdd(&sh[c0 + 3], r.w);  atomicAdd(&sh[C + c0 + 3], r2.w);
    }
    __syncthreads();
    for (int i = tid; i < 2 * C; i += 256) atomicAdd(&statsOut[i], sh[i]);
}

// ---------------- layer-3 gather (fp16, int4 csr) + gelu + pool ----------------
__global__ void k_gather_pool_h(const float* __restrict__ bias, const int* __restrict__ batch) {
    const int W = 32;
    int t = blockIdx.x * blockDim.x + threadIdx.x;
    if (t >= NN * W) return;
    int n = t / W, q = t - n * W;
    const uint2* __restrict__ hw = (const uint2*)g_hwh;
    float4 s;
    { uint2 u = hw[n * W + q];
      float2 f0 = __half22float2(*(__half2*)&u.x);
      float2 f1 = __half22float2(*(__half2*)&u.y);
      s = make_float4(f0.x, f0.y, f1.x, f1.y); }
    int j = g_rowptr[n], end = g_rowptr[n + 1];
    while (j < end && (j & 3)) acc_h(s, hw[g_csr[j++] * W + q]);
    for (; j + 8 <= end; j += 8) {
        int4 a4 = *(const int4*)&g_csr[j];
        int4 b4 = *(const int4*)&g_csr[j + 4];
        uint2 u0 = hw[a4.x*W+q], u1 = hw[a4.y*W+q], u2 = hw[a4.z*W+q], u3 = hw[a4.w*W+q];
        uint2 u4 = hw[b4.x*W+q], u5 = hw[b4.y*W+q], u6 = hw[b4.z*W+q], u7 = hw[b4.w*W+q];
        acc_h(s, u0); acc_h(s, u1); acc_h(s, u2); acc_h(s, u3);
        acc_h(s, u4); acc_h(s, u5); acc_h(s, u6); acc_h(s, u7);
    }
    if (j + 4 <= end) {
        int4 a4 = *(const int4*)&g_csr[j];
        uint2 u0 = hw[a4.x*W+q], u1 = hw[a4.y*W+q], u2 = hw[a4.z*W+q], u3 = hw[a4.w*W+q];
        acc_h(s, u0); acc_h(s, u1); acc_h(s, u2); acc_h(s, u3);
        j += 4;
    }
    for (; j < end; ++j) acc_h(s, hw[g_csr[j] * W + q]);
    float d = g_dis[n];
    float4 bb = *(const float4*)&bias[q * 4];
    int g = batch[n];
    red_add_v4(&g_pool[g * 128 + q * 4],
               geluf(fmaf(d, s.x, bb.x)), geluf(fmaf(d, s.y, bb.y)),
               geluf(fmaf(d, s.z, bb.z)), geluf(fmaf(d, s.w, bb.w)));
}

// ---------------- fused MLP head -------------------------------------------------
__global__ void k_head(const int* __restrict__ batch, const float* __restrict__ yx,
                       const float* __restrict__ lw1, const float* __restrict__ lb1,
                       const float* __restrict__ lw2, const float* __restrict__ lb2,
                       const float* __restrict__ lw3, const float* __restrict__ lb3,
                       const float* __restrict__ lw4, const float* __restrict__ lb4,
                       float* __restrict__ out) {
    int g = blockIdx.x, tid = threadIdx.x;
    __shared__ float z[136], a1[128], a2[64], a3[32];
    __shared__ int bounds[2];
    if (tid < 2) {
        int key = g + tid;
        int lo = 0, hi = NN;
        while (lo < hi) {
            int mid = (lo + hi) >> 1;
            if (batch[mid] < key) lo = mid + 1; else hi = mid;
        }
        bounds[tid] = lo;
    }
    __syncthreads();
    float inv = 1.0f / fmaxf((float)(bounds[1] - bounds[0]), 1.0f);
    for (int j = tid; j < 135; j += 128)
        z[j] = (j < 128) ? g_pool[g * 128 + j] * inv : yx[g * 7 + (j - 128)];
    __syncthreads();
    {
        float s = lb1[tid];
        #pragma unroll 5
        for (int i = 0; i < 135; ++i) s = fmaf(z[i], lw1[i * 128 + tid], s);
        a1[tid] = geluf(s);
    }
    __syncthreads();
    if (tid < 64) {
        float s = lb2[tid];
        #pragma unroll 8
        for (int i = 0; i < 128; ++i) s = fmaf(a1[i], lw2[i * 64 + tid], s);
        a2[tid] = geluf(s);
    }
    __syncthreads();
    if (tid < 32) {
        float s = lb3[tid];
        #pragma unroll 8
        for (int i = 0; i < 64; ++i) s = fmaf(a2[i], lw3[i * 32 + tid], s);
        a3[tid] = geluf(s);
    }
    __syncthreads();
    if (tid < 2) {
        float s = lb4[tid];
        #pragma unroll
        for (int i = 0; i < 32; ++i) s = fmaf(a3[i], lw4[i * 2 + tid], s);
        out[g * 2 + tid] = 1.0f / (1.0f + expf(-s));
    }
}

// ---------------- host -------------------------------------------------------------
static inline int gs(int n) { return (n + 255) / 256; }

extern "C" void kernel_launch(void* const* d_in, const int* in_sizes, int n_in,
                              void* d_out, int out_size) {
    const float* x     = (const float*)d_in[0];
    const int*   ei    = (const int*)d_in[1];
    const int*   batch = (const int*)d_in[2];
    const float* yx    = (const float*)d_in[3];
    const float* W[4]  = {(const float*)d_in[4], (const float*)d_in[6],
                          (const float*)d_in[8], (const float*)d_in[10]};
    const float* B[4]  = {(const float*)d_in[5], (const float*)d_in[7],
                          (const float*)d_in[9], (const float*)d_in[11]};
    const float* Gm[3] = {(const float*)d_in[12], (const float*)d_in[14], (const float*)d_in[16]};
    const float* Be[3] = {(const float*)d_in[13], (const float*)d_in[15], (const float*)d_in[17]};
    const float* LW[4] = {(const float*)d_in[18], (const float*)d_in[20],
                          (const float*)d_in[22], (const float*)d_in[24]};
    const float* LB[4] = {(const float*)d_in[19], (const float*)d_in[21],
                          (const float*)d_in[23], (const float*)d_in[25]};

    void *p_cnt, *p_agg, *p_pool, *p_stats;
    cudaGetSymbolAddress(&p_cnt,   g_cnt);
    cudaGetSymbolAddress(&p_agg,   g_agg);
    cudaGetSymbolAddress(&p_pool,  g_pool);
    cudaGetSymbolAddress(&p_stats, g_stats);
    float* stats = (float*)p_stats;

    cudaMemsetAsync(p_cnt,   0, NN * sizeof(int));
    cudaMemsetAsync(p_pool,  0, GG * 128 * sizeof(float));
    cudaMemsetAsync(p_stats, 0, 384 * sizeof(float));

    k_hist <<<gs(EE), 256>>>(ei);
    k_scanA<<<SCAN_B, 256>>>();
    k_scanB<<<1, 256>>>();
    k_scanC<<<SCAN_B, 256>>>(x);
    k_fill <<<gs(EE), 256>>>(ei);

    // layer 0 (conv1): rank-1 fused
    k_l0<<<gs(NN), 256>>>(W[0], B[0], stats + 0);

    // layer 1 (conv2): 16 -> 32
    k_fold<16, 32><<<2, 256>>>(Gm[0], Be[0], W[1], stats + 0);
    k_mm4<16, 32><<<gs(NN * 8), 256>>>((const float*)p_agg);
    k_gather<8><<<gs(NN * 8), 256>>>(B[1], stats + 128);

    // layer 2 (conv3): 32 -> 64
    k_fold<32, 64><<<8, 256>>>(Gm[1], Be[1], W[2], stats + 128);
    k_mm4<32, 64><<<gs(NN * 16), 256>>>((const float*)p_agg);
    k_gather<16><<<gs(NN * 16), 256>>>(B[2], stats + 256);

    // layer 3 (conv4): 64 -> 128, pool fused
    k_fold<64, 128><<<32, 256>>>(Gm[2], Be[2], W[3], stats + 256);
    k_mm4<64, 128><<<gs(NN * 32), 256>>>((const float*)p_agg);
    k_gather_pool_h<<<gs(NN * 32), 256>>>(B[3], batch);

    k_head<<<GG, 128>>>(batch, yx, LW[0], LB[0], LW[1], LB[1],
                        LW[2], LB[2], LW[3], LB[3], (float*)d_out);
}